// round 5
// baseline (speedup 1.0000x reference)
#include <cuda_runtime.h>
#include <cuda_bf16.h>
#include <cstdint>
#include <cstddef>

// ---------------------------------------------------------------------------
// Dims
// ---------------------------------------------------------------------------
constexpr int    T_STEPS = 64;
constexpr int    BATCH   = 1024;
constexpr int    HID     = 512;
constexpr int    G3      = 3 * HID;                  // 1536
constexpr size_t NROWS   = (size_t)T_STEPS * BATCH;  // 65536
constexpr int    KDIM    = 512;

// ---------------------------------------------------------------------------
// PTX helpers (arch-unconditional, sm_80-era)
// ---------------------------------------------------------------------------
__device__ __forceinline__ uint32_t smem_u32(const void* p) {
    uint32_t a;
    asm("{ .reg .u64 t; cvta.to.shared.u64 t, %1; cvt.u32.u64 %0, t; }"
        : "=r"(a) : "l"(p));
    return a;
}
#define CP16(s, g) \
    asm volatile("cp.async.cg.shared.global [%0], [%1], 16;\n" :: "r"(s), "l"(g) : "memory")
#define CP_COMMIT() asm volatile("cp.async.commit_group;\n" ::: "memory")

// exact tail-safe wait: group kc is complete afterwards
#define CP_WAIT_FOR(kc, last)                                                   \
    do {                                                                        \
        if      ((kc) + 2 <= (last)) asm volatile("cp.async.wait_group 2;" ::: "memory"); \
        else if ((kc) + 1 <= (last)) asm volatile("cp.async.wait_group 1;" ::: "memory"); \
        else                         asm volatile("cp.async.wait_group 0;" ::: "memory"); \
    } while (0)

#define LDM_X4(r, addr)                                                         \
    asm volatile("ldmatrix.sync.aligned.m8n8.x4.shared.b16 {%0,%1,%2,%3}, [%4];" \
        : "=r"((r)[0]), "=r"((r)[1]), "=r"((r)[2]), "=r"((r)[3]) : "r"(addr))

#define MMA_BF16(d, a, b0, b1)                                                  \
    asm volatile("mma.sync.aligned.m16n8k16.row.col.f32.bf16.bf16.f32 "         \
        "{%0,%1,%2,%3}, {%4,%5,%6,%7}, {%8,%9}, {%0,%1,%2,%3};"                 \
        : "+f"((d)[0]), "+f"((d)[1]), "+f"((d)[2]), "+f"((d)[3])                \
        : "r"((a)[0]), "r"((a)[1]), "r"((a)[2]), "r"((a)[3]), "r"(b0), "r"(b1))

// ---------------------------------------------------------------------------
// Scratch
// ---------------------------------------------------------------------------
__device__ float g_h  [NROWS * HID];
__device__ float g_acc[NROWS * HID];
__device__ float g_gi [NROWS * G3];
__device__ float g_gh [BATCH * G3];
__device__ float g_hst[BATCH * HID];
__device__ float g_beff[HID];

__device__ __nv_bfloat16 g_hhi[NROWS * HID], g_hlo[NROWS * HID];
__device__ __nv_bfloat16 g_xhi[NROWS * HID], g_xlo[NROWS * HID];
__device__ __nv_bfloat16 g_shi[BATCH * HID], g_slo[BATCH * HID];
__device__ __nv_bfloat16 g_w1hi[HID * HID],  g_w1lo[HID * HID];
__device__ __nv_bfloat16 g_w2hi[HID * HID],  g_w2lo[HID * HID];
__device__ __nv_bfloat16 g_wohi[HID * HID],  g_wolo[HID * HID];
__device__ __nv_bfloat16 g_wihi[G3 * HID],   g_wilo[G3 * HID];
__device__ __nv_bfloat16 g_whhi[G3 * HID],   g_whlo[G3 * HID];

// ---------------------------------------------------------------------------
// split helpers
// ---------------------------------------------------------------------------
__device__ __forceinline__ void split1(float v, __nv_bfloat16& hi, __nv_bfloat16& lo) {
    hi = __float2bfloat16(v);
    lo = __float2bfloat16(v - __bfloat162float(hi));
}
__device__ __forceinline__ void split_store_pair(__nv_bfloat16* Hi, __nv_bfloat16* Lo,
                                                 size_t i, float a, float b) {
    __nv_bfloat162 h, l;
    split1(a, h.x, l.x); split1(b, h.y, l.y);
    *reinterpret_cast<__nv_bfloat162*>(Hi + i) = h;
    *reinterpret_cast<__nv_bfloat162*>(Lo + i) = l;
}

// ===========================================================================
// FUSED kernels: BM=64, BN=512 (full N), K'=1536 (3 split segments), 512 thr.
// 16 warps laid out 1M x 16N, warp tile 64x32. 4-stage cp.async pipeline.
// Stage layout: A tile 64x32 bf16 (4KB) @ +0, B tile 512x32 bf16 (32KB) @ +4096.
// ===========================================================================
constexpr int FSTB       = 36864;          // stage bytes
constexpr int FUSED_SMEM = 4 * FSTB;       // 144 KB
constexpr int FNCHUNK    = 48;             // 3 * 512 / 32

__device__ __forceinline__ void fused_g2s(uint32_t sb, size_t bm, int kc, int tid,
    const __nv_bfloat16* __restrict__ Ahi, const __nv_bfloat16* __restrict__ Alo,
    const __nv_bfloat16* __restrict__ Bhi, const __nv_bfloat16* __restrict__ Blo)
{
    const __nv_bfloat16* A = (kc >= 16 && kc < 32) ? Alo : Ahi;
    const __nv_bfloat16* B = (kc >= 32) ? Blo : Bhi;
    const int ko = (kc & 15) * 32;
    const uint32_t st = sb + (uint32_t)(kc & 3) * FSTB;
    const int c = tid & 3;
    if (tid < 256) {
        const int r = tid >> 2;
        CP16(st + (uint32_t)(r * 64 + 16 * (c ^ ((r >> 1) & 3))),
             A + (bm + r) * KDIM + ko + c * 8);
    }
    const int r0 = tid >> 2;                    // 0..127
    #pragma unroll
    for (int i = 0; i < 4; i++) {
        const int r = r0 + i * 128;
        CP16(st + 4096 + (uint32_t)(r * 64 + 16 * (c ^ ((r >> 1) & 3))),
             B + (size_t)r * KDIM + ko + c * 8);
    }
    CP_COMMIT();
}

__device__ __forceinline__ void fused_mainloop(uint32_t sb, size_t bm,
    const __nv_bfloat16* __restrict__ Ahi, const __nv_bfloat16* __restrict__ Alo,
    const __nv_bfloat16* __restrict__ Bhi, const __nv_bfloat16* __restrict__ Blo,
    int tid, int lane, int wid, float acc[4][4][4])
{
    const int wn = wid * 32;
    #pragma unroll
    for (int kc = 0; kc < 3; kc++) fused_g2s(sb, bm, kc, tid, Ahi, Alo, Bhi, Blo);

    #pragma unroll 1
    for (int kc = 0; kc < FNCHUNK; kc++) {
        CP_WAIT_FOR(kc, FNCHUNK - 1);
        __syncthreads();
        if (kc + 3 < FNCHUNK) fused_g2s(sb, bm, kc + 3, tid, Ahi, Alo, Bhi, Blo);
        const uint32_t st = sb + (uint32_t)(kc & 3) * FSTB;

        #pragma unroll
        for (int s = 0; s < 2; s++) {
            uint32_t a[4][4], bfr[2][4];
            #pragma unroll
            for (int mf = 0; mf < 4; mf++) {
                const int ar = mf * 16 + (lane & 15);
                const int ac = s * 2 + (lane >> 4);
                LDM_X4(a[mf], st + (uint32_t)(ar * 64 + 16 * (ac ^ ((ar >> 1) & 3))));
            }
            #pragma unroll
            for (int nf16 = 0; nf16 < 2; nf16++) {
                const int br = wn + nf16 * 16 + (lane & 7) + ((lane >> 4) & 1) * 8;
                const int bc = s * 2 + ((lane >> 3) & 1);
                LDM_X4(bfr[nf16],
                       st + 4096 + (uint32_t)(br * 64 + 16 * (bc ^ ((br >> 1) & 3))));
            }
            #pragma unroll
            for (int mf = 0; mf < 4; mf++)
                #pragma unroll
                for (int nf = 0; nf < 4; nf++)
                    MMA_BF16(acc[mf][nf], a[mf],
                             bfr[nf >> 1][(nf & 1) * 2], bfr[nf >> 1][(nf & 1) * 2 + 1]);
        }
        __syncthreads();
    }
}

// accum element mapping: (row = mf*16 + (lane>>2) + 8*hv, col = wn + nf*8 + 2*(lane&3) + b)
// with value acc[mf][nf][2*hv + b].

// ---- GEMM + bias + LayerNorm + LeakyReLU -> bf16 split (used for ode L1, L2)
__global__ void __launch_bounds__(512, 1)
gemm_ln_fused(const __nv_bfloat16* __restrict__ Ahi, const __nv_bfloat16* __restrict__ Alo,
              const __nv_bfloat16* __restrict__ Bhi, const __nv_bfloat16* __restrict__ Blo,
              const float* __restrict__ bias,
              const float* __restrict__ lng, const float* __restrict__ lnb,
              __nv_bfloat16* __restrict__ Xhi, __nv_bfloat16* __restrict__ Xlo)
{
    extern __shared__ char smem[];
    const uint32_t sb = smem_u32(smem);
    const int tid = threadIdx.x, lane = tid & 31, wid = tid >> 5;
    const int wn = wid * 32;
    const size_t bm = (size_t)blockIdx.x * 64;

    float acc[4][4][4];
    #pragma unroll
    for (int i = 0; i < 4; i++)
        #pragma unroll
        for (int j = 0; j < 4; j++)
            #pragma unroll
            for (int v = 0; v < 4; v++) acc[i][j][v] = 0.f;

    fused_mainloop(sb, bm, Ahi, Alo, Bhi, Blo, tid, lane, wid, acc);

    // bias add
    #pragma unroll
    for (int nf = 0; nf < 4; nf++) {
        const int col = wn + nf * 8 + 2 * (lane & 3);
        const float b0 = bias[col], b1 = bias[col + 1];
        #pragma unroll
        for (int mf = 0; mf < 4; mf++) {
            acc[mf][nf][0] += b0; acc[mf][nf][1] += b1;
            acc[mf][nf][2] += b0; acc[mf][nf][3] += b1;
        }
    }

    float* part = reinterpret_cast<float*>(smem);          // [64][16]
    float* stat = reinterpret_cast<float*>(smem) + 1024;   // mean[64], rstd[64]

    // mean
    #pragma unroll
    for (int mf = 0; mf < 4; mf++)
        #pragma unroll
        for (int hv = 0; hv < 2; hv++) {
            float ps = 0.f;
            #pragma unroll
            for (int nf = 0; nf < 4; nf++)
                ps += acc[mf][nf][2 * hv] + acc[mf][nf][2 * hv + 1];
            ps += __shfl_xor_sync(0xffffffffu, ps, 1);
            ps += __shfl_xor_sync(0xffffffffu, ps, 2);
            if ((lane & 3) == 0)
                part[(mf * 16 + (lane >> 2) + 8 * hv) * 16 + wid] = ps;
        }
    __syncthreads();
    if (tid < 64) {
        float s = 0.f;
        #pragma unroll
        for (int j = 0; j < 16; j++) s += part[tid * 16 + j];
        stat[tid] = s * (1.0f / 512.0f);
    }
    __syncthreads();
    // var
    #pragma unroll
    for (int mf = 0; mf < 4; mf++)
        #pragma unroll
        for (int hv = 0; hv < 2; hv++) {
            const int row = mf * 16 + (lane >> 2) + 8 * hv;
            const float m = stat[row];
            float ps = 0.f;
            #pragma unroll
            for (int nf = 0; nf < 4; nf++) {
                const float d0 = acc[mf][nf][2 * hv]     - m;
                const float d1 = acc[mf][nf][2 * hv + 1] - m;
                ps += d0 * d0 + d1 * d1;
            }
            ps += __shfl_xor_sync(0xffffffffu, ps, 1);
            ps += __shfl_xor_sync(0xffffffffu, ps, 2);
            if ((lane & 3) == 0) part[row * 16 + wid] = ps;
        }
    __syncthreads();
    if (tid < 64) {
        float s = 0.f;
        #pragma unroll
        for (int j = 0; j < 16; j++) s += part[tid * 16 + j];
        stat[64 + tid] = rsqrtf(s * (1.0f / 512.0f) + 1e-5f);
    }
    __syncthreads();
    // normalize + leaky-relu + split store
    #pragma unroll
    for (int nf = 0; nf < 4; nf++) {
        const int col = wn + nf * 8 + 2 * (lane & 3);
        const float g0 = lng[col], g1 = lng[col + 1];
        const float c0 = lnb[col], c1 = lnb[col + 1];
        #pragma unroll
        for (int mf = 0; mf < 4; mf++)
            #pragma unroll
            for (int hv = 0; hv < 2; hv++) {
                const int row = mf * 16 + (lane >> 2) + 8 * hv;
                const float m = stat[row], rs = stat[64 + row];
                float y0 = fmaf((acc[mf][nf][2 * hv]     - m) * rs, g0, c0);
                float y1 = fmaf((acc[mf][nf][2 * hv + 1] - m) * rs, g1, c1);
                y0 = (y0 > 0.f) ? y0 : 0.01f * y0;
                y1 = (y1 > 0.f) ? y1 : 0.01f * y1;
                split_store_pair(Xhi, Xlo, (bm + row) * 512 + col, y0, y1);
            }
    }
}

// ---- GEMM + bias + RK4 elementwise update (used for ode Wout)
// mode0: Acc=K, Y=H+wy*K (split). mode1: Acc+=wacc*K, Y=H+wy*K (split).
// mode2: H+=(Acc+K)/24, store H fp32, Y split (Y pointers = Hhi/Hlo).
__global__ void __launch_bounds__(512, 1)
gemm_rk4_fused(const __nv_bfloat16* __restrict__ Ahi, const __nv_bfloat16* __restrict__ Alo,
               const __nv_bfloat16* __restrict__ Bhi, const __nv_bfloat16* __restrict__ Blo,
               const float* __restrict__ bias,
               float* __restrict__ H, float* __restrict__ Acc,
               __nv_bfloat16* __restrict__ Yhi, __nv_bfloat16* __restrict__ Ylo,
               float wacc, float wy, int mode)
{
    extern __shared__ char smem[];
    const uint32_t sb = smem_u32(smem);
    const int tid = threadIdx.x, lane = tid & 31, wid = tid >> 5;
    const int wn = wid * 32;
    const size_t bm = (size_t)blockIdx.x * 64;

    float acc[4][4][4];
    #pragma unroll
    for (int i = 0; i < 4; i++)
        #pragma unroll
        for (int j = 0; j < 4; j++)
            #pragma unroll
            for (int v = 0; v < 4; v++) acc[i][j][v] = 0.f;

    fused_mainloop(sb, bm, Ahi, Alo, Bhi, Blo, tid, lane, wid, acc);

    #pragma unroll
    for (int nf = 0; nf < 4; nf++) {
        const int col = wn + nf * 8 + 2 * (lane & 3);
        const float b0 = bias[col], b1 = bias[col + 1];
        #pragma unroll
        for (int mf = 0; mf < 4; mf++)
            #pragma unroll
            for (int hv = 0; hv < 2; hv++) {
                const int row = mf * 16 + (lane >> 2) + 8 * hv;
                const size_t ix = (bm + row) * 512 + col;
                const float k0 = acc[mf][nf][2 * hv]     + b0;
                const float k1 = acc[mf][nf][2 * hv + 1] + b1;
                if (mode == 0) {
                    *reinterpret_cast<float2*>(Acc + ix) = make_float2(k0, k1);
                    const float2 h2 = *reinterpret_cast<const float2*>(H + ix);
                    split_store_pair(Yhi, Ylo, ix, fmaf(wy, k0, h2.x), fmaf(wy, k1, h2.y));
                } else if (mode == 1) {
                    float2 a2 = *reinterpret_cast<const float2*>(Acc + ix);
                    a2.x = fmaf(wacc, k0, a2.x); a2.y = fmaf(wacc, k1, a2.y);
                    *reinterpret_cast<float2*>(Acc + ix) = a2;
                    const float2 h2 = *reinterpret_cast<const float2*>(H + ix);
                    split_store_pair(Yhi, Ylo, ix, fmaf(wy, k0, h2.x), fmaf(wy, k1, h2.y));
                } else {
                    const float2 a2 = *reinterpret_cast<const float2*>(Acc + ix);
                    float2 h2 = *reinterpret_cast<const float2*>(H + ix);
                    const float cc = 1.0f / 24.0f;
                    h2.x = fmaf(a2.x + k0, cc, h2.x);
                    h2.y = fmaf(a2.y + k1, cc, h2.y);
                    *reinterpret_cast<float2*>(H + ix) = h2;
                    split_store_pair(Yhi, Ylo, ix, h2.x, h2.y);
                }
            }
    }
}

// ===========================================================================
// General split-3 GEMM (bias epilogue), templated BM (128 for gi, 64 for GRU)
// BN=128, BK=32, 256 threads. grid = (N/128, M/BM).
// ===========================================================================
template<int BM>
__global__ void __launch_bounds__(256)
gemm_split3(const __nv_bfloat16* __restrict__ Ahi, const __nv_bfloat16* __restrict__ Alo,
            const __nv_bfloat16* __restrict__ Bhi, const __nv_bfloat16* __restrict__ Blo,
            const float* __restrict__ bias, float* __restrict__ C, int N)
{
    constexpr int MF  = BM / 32;            // m16 frags per warp
    constexpr int STB = BM * 64 + 8192;     // stage bytes (A + B)
    constexpr int NCHUNK = 48;

    extern __shared__ char smem[];
    const uint32_t sb = smem_u32(smem);
    const int tid  = threadIdx.x;
    const int lane = tid & 31;
    const int wid  = tid >> 5;
    const int wm   = (wid >> 2) * (BM / 2);
    const int wn   = (wid & 3) * 32;
    const size_t bm = (size_t)blockIdx.y * BM;
    const size_t bn = (size_t)blockIdx.x * 128;

    float acc[MF][4][4];
    #pragma unroll
    for (int i = 0; i < MF; i++)
        #pragma unroll
        for (int j = 0; j < 4; j++)
            #pragma unroll
            for (int v = 0; v < 4; v++) acc[i][j][v] = 0.f;

    auto Aseg = [&](int kc) { return ((kc >> 4) == 1) ? Alo : Ahi; };
    auto Bseg = [&](int kc) { return ((kc >> 4) == 2) ? Blo : Bhi; };

    auto g2s = [&](int kc) {
        const uint32_t st = sb + (uint32_t)(kc & 3) * STB;
        const int ko = (kc & 15) * 32;
        const int c  = tid & 3;
        const int r0 = tid >> 2;
        const __nv_bfloat16* A = Aseg(kc);
        const __nv_bfloat16* B = Bseg(kc);
        #pragma unroll
        for (int i = 0; i < BM / 64; i++) {
            const int r = r0 + i * 64;
            CP16(st + (uint32_t)(r * 64 + 16 * (c ^ ((r >> 1) & 3))),
                 A + (bm + r) * KDIM + ko + c * 8);
        }
        #pragma unroll
        for (int i = 0; i < 2; i++) {
            const int r = r0 + i * 64;
            CP16(st + BM * 64 + (uint32_t)(r * 64 + 16 * (c ^ ((r >> 1) & 3))),
                 B + (bn + r) * KDIM + ko + c * 8);
        }
        CP_COMMIT();
    };

    #pragma unroll
    for (int kc = 0; kc < 3; kc++) g2s(kc);

    #pragma unroll 1
    for (int kc = 0; kc < NCHUNK; kc++) {
        CP_WAIT_FOR(kc, NCHUNK - 1);
        __syncthreads();
        if (kc + 3 < NCHUNK) g2s(kc + 3);
        const uint32_t st = sb + (uint32_t)(kc & 3) * STB;

        #pragma unroll
        for (int s = 0; s < 2; s++) {
            uint32_t a[MF][4], bfr[2][4];
            #pragma unroll
            for (int mf = 0; mf < MF; mf++) {
                const int ar = wm + mf * 16 + (lane & 15);
                const int ac = s * 2 + (lane >> 4);
                LDM_X4(a[mf], st + (uint32_t)(ar * 64 + 16 * (ac ^ ((ar >> 1) & 3))));
            }
            #pragma unroll
            for (int nf16 = 0; nf16 < 2; nf16++) {
                const int br = wn + nf16 * 16 + (lane & 7) + ((lane >> 4) & 1) * 8;
                const int bc = s * 2 + ((lane >> 3) & 1);
                LDM_X4(bfr[nf16],
                       st + BM * 64 + (uint32_t)(br * 64 + 16 * (bc ^ ((br >> 1) & 3))));
            }
            #pragma unroll
            for (int mf = 0; mf < MF; mf++)
                #pragma unroll
                for (int nf = 0; nf < 4; nf++)
                    MMA_BF16(acc[mf][nf], a[mf],
                             bfr[nf >> 1][(nf & 1) * 2], bfr[nf >> 1][(nf & 1) * 2 + 1]);
        }
        __syncthreads();
    }

    #pragma unroll
    for (int mf = 0; mf < MF; mf++) {
        const size_t r0 = bm + wm + mf * 16 + (lane >> 2);
        #pragma unroll
        for (int nf = 0; nf < 4; nf++) {
            const int col = wn + nf * 8 + (lane & 3) * 2;
            const float b0 = bias[bn + col], b1 = bias[bn + col + 1];
            *reinterpret_cast<float2*>(C + r0 * N + bn + col) =
                make_float2(acc[mf][nf][0] + b0, acc[mf][nf][1] + b1);
            *reinterpret_cast<float2*>(C + (r0 + 8) * N + bn + col) =
                make_float2(acc[mf][nf][2] + b0, acc[mf][nf][3] + b1);
        }
    }
}

// ---------------------------------------------------------------------------
// Elementwise / prep kernels
// ---------------------------------------------------------------------------
__device__ __forceinline__ float block_sum512(float x, float* red, int tid) {
    #pragma unroll
    for (int o = 16; o > 0; o >>= 1) x += __shfl_xor_sync(0xffffffffu, x, o);
    __syncthreads();
    if ((tid & 31) == 0) red[tid >> 5] = x;
    __syncthreads();
    float t = 0.f;
    #pragma unroll
    for (int i = 0; i < 8; i++) t += red[i];
    return t;
}

__global__ void obs_embed(const float* __restrict__ xs, const float* __restrict__ W,
                          const float* __restrict__ bias,
                          const float* __restrict__ lg, const float* __restrict__ lb,
                          float* __restrict__ H,
                          __nv_bfloat16* __restrict__ Hhi, __nv_bfloat16* __restrict__ Hlo)
{
    __shared__ float xv[8];
    __shared__ float red[8];
    const size_t row = blockIdx.x;
    const int tid = threadIdx.x;
    const int c = 2 * tid;
    if (tid < 8) xv[tid] = xs[row * 8 + tid];
    __syncthreads();
    float2 v = *reinterpret_cast<const float2*>(bias + c);
    #pragma unroll
    for (int k = 0; k < 8; k++) {
        float2 w = *reinterpret_cast<const float2*>(W + k * 512 + c);
        v.x = fmaf(xv[k], w.x, v.x);
        v.y = fmaf(xv[k], w.y, v.y);
    }
    const float mean = block_sum512(v.x + v.y, red, tid) * (1.f / 512.f);
    const float d0 = v.x - mean, d1 = v.y - mean;
    const float rstd = rsqrtf(block_sum512(d0 * d0 + d1 * d1, red, tid) * (1.f / 512.f) + 1e-5f);
    const float2 gg = *reinterpret_cast<const float2*>(lg + c);
    const float2 bb = *reinterpret_cast<const float2*>(lb + c);
    float y0 = fmaf(d0 * rstd, gg.x, bb.x);
    float y1 = fmaf(d1 * rstd, gg.y, bb.y);
    y0 = (y0 > 0.f) ? y0 : 0.01f * y0;
    y1 = (y1 > 0.f) ? y1 : 0.01f * y1;
    *reinterpret_cast<float2*>(H + row * 512 + c) = make_float2(y0, y1);
    split_store_pair(Hhi, Hlo, row * 512 + c, y0, y1);
}

__global__ void make_bias_kernel(float* __restrict__ beff, const float* __restrict__ b1,
                                 const float* __restrict__ w1_last, float t)
{
    int n = blockIdx.x * blockDim.x + threadIdx.x;
    if (n < 512) beff[n] = fmaf(t, w1_last[n], b1[n]);
}

__global__ void gru_step(const float* __restrict__ GI, const float* __restrict__ GH,
                         float* __restrict__ Hs,
                         __nv_bfloat16* __restrict__ Shi, __nv_bfloat16* __restrict__ Slo)
{
    const int i   = blockIdx.x * blockDim.x + threadIdx.x;
    const int row = i >> 9;
    const int n   = i & 511;
    const float* gi = GI + (size_t)row * 1536;
    const float* gh = GH + (size_t)row * 1536;
    const float r  = 1.f / (1.f + expf(-(gi[n]       + gh[n])));
    const float z  = 1.f / (1.f + expf(-(gi[512 + n] + gh[512 + n])));
    const float nn = tanhf(gi[1024 + n] + r * gh[1024 + n]);
    const float h  = (1.f - z) * nn + z * Hs[i];
    Hs[i] = h;
    split1(h, Shi[i], Slo[i]);
}

__global__ void wsplit(const float* __restrict__ W,
                       __nv_bfloat16* __restrict__ Whi, __nv_bfloat16* __restrict__ Wlo,
                       int K, int N)
{
    int idx = blockIdx.x * blockDim.x + threadIdx.x;
    if (idx >= K * N) return;
    int k = idx / N, n = idx % N;
    __nv_bfloat16 hi, lo;
    split1(W[idx], hi, lo);
    Whi[(size_t)n * K + k] = hi;
    Wlo[(size_t)n * K + k] = lo;
}

__global__ void zero_state(float* __restrict__ h,
                           __nv_bfloat16* __restrict__ hi, __nv_bfloat16* __restrict__ lo)
{
    int i = blockIdx.x * blockDim.x + threadIdx.x;
    h[i] = 0.f;
    hi[i] = __float2bfloat16(0.f);
    lo[i] = __float2bfloat16(0.f);
}

__global__ void copy_kernel(float* __restrict__ dst, const float* __restrict__ src)
{
    int i = blockIdx.x * blockDim.x + threadIdx.x;
    dst[i] = src[i];
}

// ---------------------------------------------------------------------------
// Launch
// ---------------------------------------------------------------------------
extern "C" void kernel_launch(void* const* d_in, const int* in_sizes, int n_in,
                              void* d_out, int out_size)
{
    const float* xs       = (const float*)d_in[0];
    const float* obs_W    = (const float*)d_in[1];
    const float* obs_b    = (const float*)d_in[2];
    const float* obs_lg   = (const float*)d_in[3];
    const float* obs_lb   = (const float*)d_in[4];
    const float* ode_W1   = (const float*)d_in[5];   // [513, 512]
    const float* ode_b1   = (const float*)d_in[6];
    const float* ln1_g    = (const float*)d_in[7];
    const float* ln1_b    = (const float*)d_in[8];
    const float* ode_W2   = (const float*)d_in[9];
    const float* ode_b2   = (const float*)d_in[10];
    const float* ln2_g    = (const float*)d_in[11];
    const float* ln2_b    = (const float*)d_in[12];
    const float* ode_Wout = (const float*)d_in[13];
    const float* ode_bout = (const float*)d_in[14];
    const float* W_ih     = (const float*)d_in[15];  // [512, 1536]
    const float* b_ih     = (const float*)d_in[16];
    const float* W_hh     = (const float*)d_in[17];
    const float* b_hh     = (const float*)d_in[18];

    float *p_h, *p_acc, *p_gi, *p_gh, *p_hst, *p_beff;
    __nv_bfloat16 *p_hhi, *p_hlo, *p_xhi, *p_xlo, *p_shi, *p_slo;
    __nv_bfloat16 *w1h, *w1l, *w2h, *w2l, *woh, *wol, *wih, *wil, *whh, *whl;
    cudaGetSymbolAddress((void**)&p_h,    g_h);
    cudaGetSymbolAddress((void**)&p_acc,  g_acc);
    cudaGetSymbolAddress((void**)&p_gi,   g_gi);
    cudaGetSymbolAddress((void**)&p_gh,   g_gh);
    cudaGetSymbolAddress((void**)&p_hst,  g_hst);
    cudaGetSymbolAddress((void**)&p_beff, g_beff);
    cudaGetSymbolAddress((void**)&p_hhi,  g_hhi);
    cudaGetSymbolAddress((void**)&p_hlo,  g_hlo);
    cudaGetSymbolAddress((void**)&p_xhi,  g_xhi);
    cudaGetSymbolAddress((void**)&p_xlo,  g_xlo);
    cudaGetSymbolAddress((void**)&p_shi,  g_shi);
    cudaGetSymbolAddress((void**)&p_slo,  g_slo);
    cudaGetSymbolAddress((void**)&w1h,    g_w1hi);
    cudaGetSymbolAddress((void**)&w1l,    g_w1lo);
    cudaGetSymbolAddress((void**)&w2h,    g_w2hi);
    cudaGetSymbolAddress((void**)&w2l,    g_w2lo);
    cudaGetSymbolAddress((void**)&woh,    g_wohi);
    cudaGetSymbolAddress((void**)&wol,    g_wolo);
    cudaGetSymbolAddress((void**)&wih,    g_wihi);
    cudaGetSymbolAddress((void**)&wil,    g_wilo);
    cudaGetSymbolAddress((void**)&whh,    g_whhi);
    cudaGetSymbolAddress((void**)&whl,    g_whlo);

    cudaFuncSetAttribute(gemm_ln_fused,  cudaFuncAttributeMaxDynamicSharedMemorySize, FUSED_SMEM);
    cudaFuncSetAttribute(gemm_rk4_fused, cudaFuncAttributeMaxDynamicSharedMemorySize, FUSED_SMEM);
    cudaFuncSetAttribute(gemm_split3<128>, cudaFuncAttributeMaxDynamicSharedMemorySize,
                         4 * (128 * 64 + 8192));
    cudaFuncSetAttribute(gemm_split3<64>, cudaFuncAttributeMaxDynamicSharedMemorySize,
                         4 * (64 * 64 + 8192));

    const int M = (int)NROWS;

    // Weight prep (transpose + bf16 split). W1 uses only its first 512 rows.
    wsplit<<<(512 * 512) / 256, 256>>>(ode_W1,   w1h, w1l, 512, 512);
    wsplit<<<(512 * 512) / 256, 256>>>(ode_W2,   w2h, w2l, 512, 512);
    wsplit<<<(512 * 512) / 256, 256>>>(ode_Wout, woh, wol, 512, 512);
    wsplit<<<(512 * 1536) / 256, 256>>>(W_ih, wih, wil, 512, 1536);
    wsplit<<<(512 * 1536) / 256, 256>>>(W_hh, whh, whl, 512, 1536);

    // obs embedding (ODE initial conditions)
    obs_embed<<<M, 256>>>(xs, obs_W, obs_b, obs_lg, obs_lb, p_h, p_hhi, p_hlo);

    const int FG = M / 64;                    // 1024 CTAs for fused GEMMs

    // Batched RK4 over ALL timesteps (effective batch 65536), fully fused
    const float dt = 0.25f;
    const float toff[4] = {0.f, 0.125f, 0.125f, 0.25f};
    for (int s = 0; s < 4; s++) {
        const float t0 = (float)s * dt;
        for (int st = 0; st < 4; st++) {
            make_bias_kernel<<<2, 256>>>(p_beff, ode_b1, ode_W1 + 512 * 512, t0 + toff[st]);
            const __nv_bfloat16* Ah = (st == 0) ? p_hhi : p_xhi;
            const __nv_bfloat16* Al = (st == 0) ? p_hlo : p_xlo;
            gemm_ln_fused<<<FG, 512, FUSED_SMEM>>>(Ah, Al, w1h, w1l, p_beff,
                                                   ln1_g, ln1_b, p_xhi, p_xlo);
            gemm_ln_fused<<<FG, 512, FUSED_SMEM>>>(p_xhi, p_xlo, w2h, w2l, ode_b2,
                                                   ln2_g, ln2_b, p_xhi, p_xlo);
            if (st < 3) {
                const float wa = (st == 0) ? 1.f : 2.f;
                const float wy = (st == 2) ? 0.25f : 0.125f;
                gemm_rk4_fused<<<FG, 512, FUSED_SMEM>>>(p_xhi, p_xlo, woh, wol, ode_bout,
                                                        p_h, p_acc, p_xhi, p_xlo,
                                                        wa, wy, (st == 0) ? 0 : 1);
            } else {
                gemm_rk4_fused<<<FG, 512, FUSED_SMEM>>>(p_xhi, p_xlo, woh, wol, ode_bout,
                                                        p_h, p_acc, p_hhi, p_hlo,
                                                        1.f, 0.f, 2);
            }
        }
    }

    // Input gates for all timesteps in one GEMM
    dim3 gGi(1536 / 128, M / 128);
    gemm_split3<128><<<gGi, 256, 4 * (128 * 64 + 8192)>>>(p_hhi, p_hlo, wih, wil,
                                                          b_ih, p_gi, 1536);

    // Sequential GRU (BM=64 for 2x more CTAs on the latency-bound path)
    zero_state<<<(BATCH * HID) / 256, 256>>>(p_hst, p_shi, p_slo);
    dim3 gGru(1536 / 128, BATCH / 64);
    for (int t = 0; t < T_STEPS; t++) {
        gemm_split3<64><<<gGru, 256, 4 * (64 * 64 + 8192)>>>(p_shi, p_slo, whh, whl,
                                                             b_hh, p_gh, 1536);
        gru_step<<<(BATCH * HID) / 256, 256>>>(p_gi + (size_t)t * BATCH * G3, p_gh,
                                               p_hst, p_shi, p_slo);
    }

    copy_kernel<<<(BATCH * HID) / 256, 256>>>((float*)d_out, p_hst);
}

// round 6
// speedup vs baseline: 1.5220x; 1.5220x over previous
#include <cuda_runtime.h>
#include <cuda_fp16.h>
#include <cstdint>
#include <cstddef>

// ---------------------------------------------------------------------------
// Dims
// ---------------------------------------------------------------------------
constexpr int    T_STEPS = 64;
constexpr int    BATCH   = 1024;
constexpr int    HID     = 512;
constexpr int    G3      = 3 * HID;                  // 1536
constexpr size_t NROWS   = (size_t)T_STEPS * BATCH;  // 65536
constexpr int    KDIM    = 512;

// ---------------------------------------------------------------------------
// PTX helpers (arch-unconditional, sm_80-era)
// ---------------------------------------------------------------------------
__device__ __forceinline__ uint32_t smem_u32(const void* p) {
    uint32_t a;
    asm("{ .reg .u64 t; cvta.to.shared.u64 t, %1; cvt.u32.u64 %0, t; }"
        : "=r"(a) : "l"(p));
    return a;
}
#define CP16(s, g) \
    asm volatile("cp.async.cg.shared.global [%0], [%1], 16;\n" :: "r"(s), "l"(g) : "memory")
#define CP_COMMIT() asm volatile("cp.async.commit_group;\n" ::: "memory")
#define CP_WAIT_N(n) asm volatile("cp.async.wait_group %0;" :: "n"(n) : "memory")

#define LDM_X4(r, addr)                                                         \
    asm volatile("ldmatrix.sync.aligned.m8n8.x4.shared.b16 {%0,%1,%2,%3}, [%4];" \
        : "=r"((r)[0]), "=r"((r)[1]), "=r"((r)[2]), "=r"((r)[3]) : "r"(addr))

#define MMA_F16(d, a, b0, b1)                                                   \
    asm volatile("mma.sync.aligned.m16n8k16.row.col.f32.f16.f16.f32 "           \
        "{%0,%1,%2,%3}, {%4,%5,%6,%7}, {%8,%9}, {%0,%1,%2,%3};"                 \
        : "+f"((d)[0]), "+f"((d)[1]), "+f"((d)[2]), "+f"((d)[3])                \
        : "r"((a)[0]), "r"((a)[1]), "r"((a)[2]), "r"((a)[3]), "r"(b0), "r"(b1))

// ---------------------------------------------------------------------------
// Scratch
// ---------------------------------------------------------------------------
__device__ float g_h  [NROWS * HID];   // fp32 ODE state (kept exact)
__device__ float g_acc[NROWS * HID];
__device__ float g_k  [NROWS * HID];
__device__ float g_z  [NROWS * HID];
__device__ float g_gi [NROWS * G3];
__device__ float g_gh [BATCH * G3];
__device__ float g_hst[BATCH * HID];
__device__ float g_beff[HID];

__device__ __half g_hhi[NROWS * HID], g_hlo[NROWS * HID];
__device__ __half g_xhi[NROWS * HID], g_xlo[NROWS * HID];
__device__ __half g_shi[BATCH * HID], g_slo[BATCH * HID];
__device__ __half g_w1hi[HID * HID],  g_w1lo[HID * HID];
__device__ __half g_w2hi[HID * HID],  g_w2lo[HID * HID];
__device__ __half g_wohi[HID * HID],  g_wolo[HID * HID];
__device__ __half g_wihi[G3 * HID],   g_wilo[G3 * HID];
__device__ __half g_whhi[G3 * HID],   g_whlo[G3 * HID];

// ---------------------------------------------------------------------------
// fp16 split helpers
// ---------------------------------------------------------------------------
__device__ __forceinline__ void split1h(float v, __half& hi, __half& lo) {
    hi = __float2half(v);
    lo = __float2half(v - __half2float(hi));
}
__device__ __forceinline__ void split_store_pair(__half* Hi, __half* Lo,
                                                 size_t i, float a, float b) {
    __half2 h, l;
    split1h(a, h.x, l.x); split1h(b, h.y, l.y);
    *reinterpret_cast<__half2*>(Hi + i) = h;
    *reinterpret_cast<__half2*>(Lo + i) = l;
}

// ===========================================================================
// fp16 split GEMM:  C[M,N] = A[M,512] @ B^T + bias, B pre-transposed [N,512].
// PRODUCTS==2:  C = Ah*(Bh+Bl)            (drops fresh fp16 rounding of A)
// PRODUCTS==3:  C = Ah*(Bh+Bl) + Al*Bh    (residual ~2^-22)
// BM x 128 tile, BK=32, 16 k-chunks, 256 threads (8 warps 2Mx4N, warp BM/2 x 32).
// Stages: 4 (P2) / 3 (P3); ONE __syncthreads per chunk.
// ===========================================================================
template<int BM, int PRODUCTS>
__global__ void __launch_bounds__(256, PRODUCTS == 2 ? 2 : 1)
gemm_f16(const __half* __restrict__ Ahi, const __half* __restrict__ Alo,
         const __half* __restrict__ Bhi, const __half* __restrict__ Blo,
         const float* __restrict__ bias, float* __restrict__ C, int N)
{
    constexpr int MF    = BM / 32;
    constexpr int AB    = BM * 64;                 // bytes of one A tile
    constexpr int ASETS = (PRODUCTS == 3) ? 2 : 1;
    constexpr int STB   = ASETS * AB + 16384;      // + Bhi 8K + Blo 8K
    constexpr int S     = (PRODUCTS == 2) ? 4 : 3;

    extern __shared__ char smem[];
    const uint32_t sb = smem_u32(smem);
    const int tid  = threadIdx.x;
    const int lane = tid & 31;
    const int wid  = tid >> 5;
    const int wm   = (wid >> 2) * (BM / 2);
    const int wn   = (wid & 3) * 32;
    const size_t bm = (size_t)blockIdx.y * BM;
    const size_t bn = (size_t)blockIdx.x * 128;

    float acc[MF][4][4];
    #pragma unroll
    for (int i = 0; i < MF; i++)
        #pragma unroll
        for (int j = 0; j < 4; j++)
            #pragma unroll
            for (int v = 0; v < 4; v++) acc[i][j][v] = 0.f;

    auto g2s = [&](int kc) {
        const uint32_t st = sb + (uint32_t)(kc % S) * STB;
        const int ko = kc * 32;
        const int c  = tid & 3;
        const int r0 = tid >> 2;
        #pragma unroll
        for (int i = 0; i < BM / 64; i++) {
            const int r = r0 + i * 64;
            const uint32_t sw = (uint32_t)(r * 64 + 16 * (c ^ ((r >> 1) & 3)));
            CP16(st + sw, Ahi + (bm + r) * KDIM + ko + c * 8);
            if constexpr (PRODUCTS == 3)
                CP16(st + AB + sw, Alo + (bm + r) * KDIM + ko + c * 8);
        }
        #pragma unroll
        for (int i = 0; i < 2; i++) {
            const int r = r0 + i * 64;
            const uint32_t sw = (uint32_t)(r * 64 + 16 * (c ^ ((r >> 1) & 3)));
            CP16(st + ASETS * AB + sw,        Bhi + (bn + r) * KDIM + ko + c * 8);
            CP16(st + ASETS * AB + 8192 + sw, Blo + (bn + r) * KDIM + ko + c * 8);
        }
        CP_COMMIT();
    };

    #pragma unroll
    for (int kc = 0; kc < S - 1; kc++) g2s(kc);

    #pragma unroll 1
    for (int kc = 0; kc < 16; kc++) {
        if constexpr (S == 4) {
            if (kc <= 13) CP_WAIT_N(2);
            else if (kc == 14) CP_WAIT_N(1);
            else CP_WAIT_N(0);
        } else {
            if (kc <= 14) CP_WAIT_N(1);
            else CP_WAIT_N(0);
        }
        __syncthreads();
        if (kc + S - 1 < 16) g2s(kc + S - 1);
        const uint32_t st = sb + (uint32_t)(kc % S) * STB;

        #pragma unroll
        for (int s = 0; s < 2; s++) {
            uint32_t ah[MF][4], al[MF][4], bh[2][4], bl[2][4];
            #pragma unroll
            for (int mf = 0; mf < MF; mf++) {
                const int ar = wm + mf * 16 + (lane & 15);
                const int ac = s * 2 + (lane >> 4);
                const uint32_t sw = (uint32_t)(ar * 64 + 16 * (ac ^ ((ar >> 1) & 3)));
                LDM_X4(ah[mf], st + sw);
                if constexpr (PRODUCTS == 3) LDM_X4(al[mf], st + AB + sw);
            }
            #pragma unroll
            for (int nf16 = 0; nf16 < 2; nf16++) {
                const int br = wn + nf16 * 16 + (lane & 7) + ((lane >> 4) & 1) * 8;
                const int bc = s * 2 + ((lane >> 3) & 1);
                const uint32_t sw = (uint32_t)(br * 64 + 16 * (bc ^ ((br >> 1) & 3)));
                LDM_X4(bh[nf16], st + ASETS * AB + sw);
                LDM_X4(bl[nf16], st + ASETS * AB + 8192 + sw);
            }
            #pragma unroll
            for (int mf = 0; mf < MF; mf++)
                #pragma unroll
                for (int nf = 0; nf < 4; nf++) {
                    const uint32_t b0h = bh[nf >> 1][(nf & 1) * 2];
                    const uint32_t b1h = bh[nf >> 1][(nf & 1) * 2 + 1];
                    const uint32_t b0l = bl[nf >> 1][(nf & 1) * 2];
                    const uint32_t b1l = bl[nf >> 1][(nf & 1) * 2 + 1];
                    MMA_F16(acc[mf][nf], ah[mf], b0h, b1h);
                    MMA_F16(acc[mf][nf], ah[mf], b0l, b1l);
                    if constexpr (PRODUCTS == 3)
                        MMA_F16(acc[mf][nf], al[mf], b0h, b1h);
                }
        }
    }

    // Epilogue: bias add, fp32 store
    #pragma unroll
    for (int mf = 0; mf < MF; mf++) {
        const size_t r0 = bm + wm + mf * 16 + (lane >> 2);
        #pragma unroll
        for (int nf = 0; nf < 4; nf++) {
            const int col = wn + nf * 8 + (lane & 3) * 2;
            const float b0 = bias[bn + col], b1 = bias[bn + col + 1];
            *reinterpret_cast<float2*>(C + r0 * N + bn + col) =
                make_float2(acc[mf][nf][0] + b0, acc[mf][nf][1] + b1);
            *reinterpret_cast<float2*>(C + (r0 + 8) * N + bn + col) =
                make_float2(acc[mf][nf][2] + b0, acc[mf][nf][3] + b1);
        }
    }
}

constexpr int SMEM_P2_128 = 4 * (1 * 128 * 64 + 16384);   // 98304
constexpr int SMEM_P3_128 = 3 * (2 * 128 * 64 + 16384);   // 98304
constexpr int SMEM_P3_64  = 3 * (2 * 64 * 64 + 16384);    // 73728

// ---------------------------------------------------------------------------
// LayerNorm(512)+LeakyReLU, warp-per-row. fp32 in -> fp16 split out.
// block 256 = 8 rows; grid = rows/8.
// ---------------------------------------------------------------------------
__global__ void ln_lrelu_split(const float* __restrict__ Z,
                               const float* __restrict__ g, const float* __restrict__ b,
                               __half* __restrict__ Xhi, __half* __restrict__ Xlo)
{
    const int lane = threadIdx.x & 31;
    const size_t row = (size_t)blockIdx.x * 8 + (threadIdx.x >> 5);
    const float* z = Z + row * 512;

    float4 v[4];
    #pragma unroll
    for (int i = 0; i < 4; i++)
        v[i] = *reinterpret_cast<const float4*>(z + i * 128 + lane * 4);

    float s = 0.f;
    #pragma unroll
    for (int i = 0; i < 4; i++) s += v[i].x + v[i].y + v[i].z + v[i].w;
    #pragma unroll
    for (int o = 16; o > 0; o >>= 1) s += __shfl_xor_sync(0xffffffffu, s, o);
    const float mean = s * (1.0f / 512.0f);

    float q = 0.f;
    #pragma unroll
    for (int i = 0; i < 4; i++) {
        const float d0 = v[i].x - mean, d1 = v[i].y - mean;
        const float d2 = v[i].z - mean, d3 = v[i].w - mean;
        q += d0 * d0 + d1 * d1 + d2 * d2 + d3 * d3;
    }
    #pragma unroll
    for (int o = 16; o > 0; o >>= 1) q += __shfl_xor_sync(0xffffffffu, q, o);
    const float rstd = rsqrtf(q * (1.0f / 512.0f) + 1e-5f);

    #pragma unroll
    for (int i = 0; i < 4; i++) {
        const int c = i * 128 + lane * 4;
        const float4 gg = *reinterpret_cast<const float4*>(g + c);
        const float4 bb = *reinterpret_cast<const float4*>(b + c);
        float y0 = fmaf((v[i].x - mean) * rstd, gg.x, bb.x);
        float y1 = fmaf((v[i].y - mean) * rstd, gg.y, bb.y);
        float y2 = fmaf((v[i].z - mean) * rstd, gg.z, bb.z);
        float y3 = fmaf((v[i].w - mean) * rstd, gg.w, bb.w);
        y0 = (y0 > 0.f) ? y0 : 0.01f * y0;
        y1 = (y1 > 0.f) ? y1 : 0.01f * y1;
        y2 = (y2 > 0.f) ? y2 : 0.01f * y2;
        y3 = (y3 > 0.f) ? y3 : 0.01f * y3;
        split_store_pair(Xhi, Xlo, row * 512 + c,     y0, y1);
        split_store_pair(Xhi, Xlo, row * 512 + c + 2, y2, y3);
    }
}

// ---------------------------------------------------------------------------
// obs -> hidden: Linear(8->512)+LN+LeakyReLU; fp32 H + fp16 split
// ---------------------------------------------------------------------------
__device__ __forceinline__ float block_sum512(float x, float* red, int tid) {
    #pragma unroll
    for (int o = 16; o > 0; o >>= 1) x += __shfl_xor_sync(0xffffffffu, x, o);
    __syncthreads();
    if ((tid & 31) == 0) red[tid >> 5] = x;
    __syncthreads();
    float t = 0.f;
    #pragma unroll
    for (int i = 0; i < 8; i++) t += red[i];
    return t;
}

__global__ void obs_embed(const float* __restrict__ xs, const float* __restrict__ W,
                          const float* __restrict__ bias,
                          const float* __restrict__ lg, const float* __restrict__ lb,
                          float* __restrict__ H,
                          __half* __restrict__ Hhi, __half* __restrict__ Hlo)
{
    __shared__ float xv[8];
    __shared__ float red[8];
    const size_t row = blockIdx.x;
    const int tid = threadIdx.x;
    const int c = 2 * tid;
    if (tid < 8) xv[tid] = xs[row * 8 + tid];
    __syncthreads();
    float2 v = *reinterpret_cast<const float2*>(bias + c);
    #pragma unroll
    for (int k = 0; k < 8; k++) {
        float2 w = *reinterpret_cast<const float2*>(W + k * 512 + c);
        v.x = fmaf(xv[k], w.x, v.x);
        v.y = fmaf(xv[k], w.y, v.y);
    }
    const float mean = block_sum512(v.x + v.y, red, tid) * (1.f / 512.f);
    const float d0 = v.x - mean, d1 = v.y - mean;
    const float rstd = rsqrtf(block_sum512(d0 * d0 + d1 * d1, red, tid) * (1.f / 512.f) + 1e-5f);
    const float2 gg = *reinterpret_cast<const float2*>(lg + c);
    const float2 bb = *reinterpret_cast<const float2*>(lb + c);
    float y0 = fmaf(d0 * rstd, gg.x, bb.x);
    float y1 = fmaf(d1 * rstd, gg.y, bb.y);
    y0 = (y0 > 0.f) ? y0 : 0.01f * y0;
    y1 = (y1 > 0.f) ? y1 : 0.01f * y1;
    *reinterpret_cast<float2*>(H + row * 512 + c) = make_float2(y0, y1);
    split_store_pair(Hhi, Hlo, row * 512 + c, y0, y1);
}

__global__ void make_bias_kernel(float* __restrict__ beff, const float* __restrict__ b1,
                                 const float* __restrict__ w1_last, float t)
{
    int n = blockIdx.x * blockDim.x + threadIdx.x;
    if (n < 512) beff[n] = fmaf(t, w1_last[n], b1[n]);
}

// RK4 bookkeeping. mode0: Acc=K, Y=H+wy*K (split). mode1: Acc+=wacc*K, Y split.
// mode2: H += (Acc+K)/24, write H fp32 + split.
__global__ void rk4_update(const float* __restrict__ Ks, float* __restrict__ Acc,
                           float* __restrict__ H,
                           __half* __restrict__ Yhi, __half* __restrict__ Ylo,
                           float wacc, float wy, int mode)
{
    const size_t i = ((size_t)blockIdx.x * blockDim.x + threadIdx.x) * 4;
    float4 k = *reinterpret_cast<const float4*>(Ks + i);
    float4 h = *reinterpret_cast<const float4*>(H + i);
    if (mode == 0) {
        *reinterpret_cast<float4*>(Acc + i) = k;
        split_store_pair(Yhi, Ylo, i,     fmaf(wy, k.x, h.x), fmaf(wy, k.y, h.y));
        split_store_pair(Yhi, Ylo, i + 2, fmaf(wy, k.z, h.z), fmaf(wy, k.w, h.w));
    } else if (mode == 1) {
        float4 a = *reinterpret_cast<const float4*>(Acc + i);
        a.x = fmaf(wacc, k.x, a.x); a.y = fmaf(wacc, k.y, a.y);
        a.z = fmaf(wacc, k.z, a.z); a.w = fmaf(wacc, k.w, a.w);
        *reinterpret_cast<float4*>(Acc + i) = a;
        split_store_pair(Yhi, Ylo, i,     fmaf(wy, k.x, h.x), fmaf(wy, k.y, h.y));
        split_store_pair(Yhi, Ylo, i + 2, fmaf(wy, k.z, h.z), fmaf(wy, k.w, h.w));
    } else {
        float4 a = *reinterpret_cast<const float4*>(Acc + i);
        const float cc = 1.0f / 24.0f;
        h.x = fmaf(a.x + k.x, cc, h.x); h.y = fmaf(a.y + k.y, cc, h.y);
        h.z = fmaf(a.z + k.z, cc, h.z); h.w = fmaf(a.w + k.w, cc, h.w);
        *reinterpret_cast<float4*>(H + i) = h;
        split_store_pair(Yhi, Ylo, i,     h.x, h.y);
        split_store_pair(Yhi, Ylo, i + 2, h.z, h.w);
    }
}

// GRU elementwise (torch gate order r,z,n); updates fp32 h + fp16 split
__global__ void gru_step(const float* __restrict__ GI, const float* __restrict__ GH,
                         float* __restrict__ Hs,
                         __half* __restrict__ Shi, __half* __restrict__ Slo)
{
    const int i   = blockIdx.x * blockDim.x + threadIdx.x;
    const int row = i >> 9;
    const int n   = i & 511;
    const float* gi = GI + (size_t)row * 1536;
    const float* gh = GH + (size_t)row * 1536;
    const float r  = 1.f / (1.f + expf(-(gi[n]       + gh[n])));
    const float z  = 1.f / (1.f + expf(-(gi[512 + n] + gh[512 + n])));
    const float nn = tanhf(gi[1024 + n] + r * gh[1024 + n]);
    const float h  = (1.f - z) * nn + z * Hs[i];
    Hs[i] = h;
    split1h(h, Shi[i], Slo[i]);
}

// W[K,N] (fp32 row-major) -> Whi/Wlo[N,K] fp16 split (transposed)
__global__ void wsplit(const float* __restrict__ W,
                       __half* __restrict__ Whi, __half* __restrict__ Wlo,
                       int K, int N)
{
    int idx = blockIdx.x * blockDim.x + threadIdx.x;
    if (idx >= K * N) return;
    int k = idx / N, n = idx % N;
    __half hi, lo;
    split1h(W[idx], hi, lo);
    Whi[(size_t)n * K + k] = hi;
    Wlo[(size_t)n * K + k] = lo;
}

__global__ void zero_state(float* __restrict__ h,
                           __half* __restrict__ hi, __half* __restrict__ lo)
{
    int i = blockIdx.x * blockDim.x + threadIdx.x;
    h[i] = 0.f;
    hi[i] = __float2half(0.f);
    lo[i] = __float2half(0.f);
}

__global__ void copy_kernel(float* __restrict__ dst, const float* __restrict__ src)
{
    int i = blockIdx.x * blockDim.x + threadIdx.x;
    dst[i] = src[i];
}

// ---------------------------------------------------------------------------
// Launch
// ---------------------------------------------------------------------------
extern "C" void kernel_launch(void* const* d_in, const int* in_sizes, int n_in,
                              void* d_out, int out_size)
{
    const float* xs       = (const float*)d_in[0];
    const float* obs_W    = (const float*)d_in[1];
    const float* obs_b    = (const float*)d_in[2];
    const float* obs_lg   = (const float*)d_in[3];
    const float* obs_lb   = (const float*)d_in[4];
    const float* ode_W1   = (const float*)d_in[5];   // [513, 512]
    const float* ode_b1   = (const float*)d_in[6];
    const float* ln1_g    = (const float*)d_in[7];
    const float* ln1_b    = (const float*)d_in[8];
    const float* ode_W2   = (const float*)d_in[9];
    const float* ode_b2   = (const float*)d_in[10];
    const float* ln2_g    = (const float*)d_in[11];
    const float* ln2_b    = (const float*)d_in[12];
    const float* ode_Wout = (const float*)d_in[13];
    const float* ode_bout = (const float*)d_in[14];
    const float* W_ih     = (const float*)d_in[15];  // [512, 1536]
    const float* b_ih     = (const float*)d_in[16];
    const float* W_hh     = (const float*)d_in[17];
    const float* b_hh     = (const float*)d_in[18];

    float *p_h, *p_acc, *p_k, *p_z, *p_gi, *p_gh, *p_hst, *p_beff;
    __half *p_hhi, *p_hlo, *p_xhi, *p_xlo, *p_shi, *p_slo;
    __half *w1h, *w1l, *w2h, *w2l, *woh, *wol, *wih, *wil, *whh, *whl;
    cudaGetSymbolAddress((void**)&p_h,    g_h);
    cudaGetSymbolAddress((void**)&p_acc,  g_acc);
    cudaGetSymbolAddress((void**)&p_k,    g_k);
    cudaGetSymbolAddress((void**)&p_z,    g_z);
    cudaGetSymbolAddress((void**)&p_gi,   g_gi);
    cudaGetSymbolAddress((void**)&p_gh,   g_gh);
    cudaGetSymbolAddress((void**)&p_hst,  g_hst);
    cudaGetSymbolAddress((void**)&p_beff, g_beff);
    cudaGetSymbolAddress((void**)&p_hhi,  g_hhi);
    cudaGetSymbolAddress((void**)&p_hlo,  g_hlo);
    cudaGetSymbolAddress((void**)&p_xhi,  g_xhi);
    cudaGetSymbolAddress((void**)&p_xlo,  g_xlo);
    cudaGetSymbolAddress((void**)&p_shi,  g_shi);
    cudaGetSymbolAddress((void**)&p_slo,  g_slo);
    cudaGetSymbolAddress((void**)&w1h,    g_w1hi);
    cudaGetSymbolAddress((void**)&w1l,    g_w1lo);
    cudaGetSymbolAddress((void**)&w2h,    g_w2hi);
    cudaGetSymbolAddress((void**)&w2l,    g_w2lo);
    cudaGetSymbolAddress((void**)&woh,    g_wohi);
    cudaGetSymbolAddress((void**)&wol,    g_wolo);
    cudaGetSymbolAddress((void**)&wih,    g_wihi);
    cudaGetSymbolAddress((void**)&wil,    g_wilo);
    cudaGetSymbolAddress((void**)&whh,    g_whhi);
    cudaGetSymbolAddress((void**)&whl,    g_whlo);

    cudaFuncSetAttribute(gemm_f16<128,2>, cudaFuncAttributeMaxDynamicSharedMemorySize, SMEM_P2_128);
    cudaFuncSetAttribute(gemm_f16<128,3>, cudaFuncAttributeMaxDynamicSharedMemorySize, SMEM_P3_128);
    cudaFuncSetAttribute(gemm_f16<64,3>,  cudaFuncAttributeMaxDynamicSharedMemorySize, SMEM_P3_64);

    const int M = (int)NROWS;

    // Weight prep (transpose + fp16 split). W1 uses only its first 512 rows.
    wsplit<<<(512 * 512) / 256, 256>>>(ode_W1,   w1h, w1l, 512, 512);
    wsplit<<<(512 * 512) / 256, 256>>>(ode_W2,   w2h, w2l, 512, 512);
    wsplit<<<(512 * 512) / 256, 256>>>(ode_Wout, woh, wol, 512, 512);
    wsplit<<<(512 * 1536) / 256, 256>>>(W_ih, wih, wil, 512, 1536);
    wsplit<<<(512 * 1536) / 256, 256>>>(W_hh, whh, whl, 512, 1536);

    // obs embedding (ODE initial conditions)
    obs_embed<<<M, 256>>>(xs, obs_W, obs_b, obs_lg, obs_lb, p_h, p_hhi, p_hlo);

    dim3 gBig(512 / 128,  M / 128);       // (4, 512)
    dim3 gGi (1536 / 128, M / 128);       // (12, 512)
    dim3 gGru(1536 / 128, BATCH / 64);    // (12, 16)
    const int EW = (int)(NROWS * HID / (256 * 4));
    const int LNG = M / 8;

    // Batched RK4 over ALL timesteps (effective batch 65536)
    const float dt = 0.25f;
    const float toff[4] = {0.f, 0.125f, 0.125f, 0.25f};
    for (int s = 0; s < 4; s++) {
        const float t0 = (float)s * dt;
        for (int st = 0; st < 4; st++) {
            make_bias_kernel<<<2, 256>>>(p_beff, ode_b1, ode_W1 + 512 * 512, t0 + toff[st]);
            const __half* Ah = (st == 0) ? p_hhi : p_xhi;
            const __half* Al = (st == 0) ? p_hlo : p_xlo;
            gemm_f16<128,2><<<gBig, 256, SMEM_P2_128>>>(Ah, Al, w1h, w1l, p_beff, p_z, 512);
            ln_lrelu_split<<<LNG, 256>>>(p_z, ln1_g, ln1_b, p_xhi, p_xlo);
            gemm_f16<128,2><<<gBig, 256, SMEM_P2_128>>>(p_xhi, p_xlo, w2h, w2l, ode_b2, p_z, 512);
            ln_lrelu_split<<<LNG, 256>>>(p_z, ln2_g, ln2_b, p_xhi, p_xlo);
            gemm_f16<128,3><<<gBig, 256, SMEM_P3_128>>>(p_xhi, p_xlo, woh, wol, ode_bout, p_k, 512);
            if      (st == 0) rk4_update<<<EW, 256>>>(p_k, p_acc, p_h, p_xhi, p_xlo, 1.f, 0.125f, 0);
            else if (st == 1) rk4_update<<<EW, 256>>>(p_k, p_acc, p_h, p_xhi, p_xlo, 2.f, 0.125f, 1);
            else if (st == 2) rk4_update<<<EW, 256>>>(p_k, p_acc, p_h, p_xhi, p_xlo, 2.f, 0.25f,  1);
            else              rk4_update<<<EW, 256>>>(p_k, p_acc, p_h, p_hhi, p_hlo, 1.f, 0.f,    2);
        }
    }

    // Input gates for all timesteps in one GEMM (3-product: near-exact)
    gemm_f16<128,3><<<gGi, 256, SMEM_P3_128>>>(p_hhi, p_hlo, wih, wil, b_ih, p_gi, 1536);

    // Sequential GRU (3-product: near-exact)
    zero_state<<<(BATCH * HID) / 256, 256>>>(p_hst, p_shi, p_slo);
    for (int t = 0; t < T_STEPS; t++) {
        gemm_f16<64,3><<<gGru, 256, SMEM_P3_64>>>(p_shi, p_slo, whh, whl, b_hh, p_gh, 1536);
        gru_step<<<(BATCH * HID) / 256, 256>>>(p_gi + (size_t)t * BATCH * G3, p_gh,
                                               p_hst, p_shi, p_slo);
    }

    copy_kernel<<<(BATCH * HID) / 256, 256>>>((float*)d_out, p_hst);
}